// round 5
// baseline (speedup 1.0000x reference)
#include <cuda_runtime.h>

// Sorted segment-sum: pred_rgb[r] = sum over samples s of ray r of w_s * rgb_s
// Round 5: coalesce the rgb stream via smem staging.
//  - R4 state: warp tile = 128 samples, lane chunk = 4; seg/w coalesced
//    int4/float4; rgb was 3x float4 per lane at 48B stride (36 L1tex
//    wavefronts/tile vs ideal 12) -> excess L1tex queue pressure.
//  - Now: warp cooperatively loads its 1536B rgb span with 3 lane-contiguous
//    LDG.128 (12 wavefronts), stages in smem, __syncwarp, reads back per-lane
//    float4 x3 at 48B stride (LDS.128 conflict-free: per phase, start banks
//    12l mod 32 cover all 32 banks once). No change in DRAM traffic.
//  - Rest unchanged: register accumulation, warp segmented suffix reduction,
//    head-lane RED; cudaMemsetAsync zeroes the poisoned output.

static constexpr int WARPS_PER_BLOCK = 8;   // blockDim 256

__global__ void __launch_bounds__(256) integrate_kernel(
    const int*   __restrict__ seg,
    const float* __restrict__ rgb,
    const float* __restrict__ w,
    float*       __restrict__ out,
    int n)
{
    __shared__ float4 sbuf[WARPS_PER_BLOCK][96];   // 1536B per warp, 12KB/block

    const int lane = threadIdx.x & 31;
    const int wib  = threadIdx.x >> 5;
    const long long warp_global =
        ((long long)blockIdx.x * blockDim.x + threadIdx.x) >> 5;
    const long long tileBase = warp_global * 128;
    if (tileBase >= n) return;            // warp-uniform exit only

    const long long base  = tileBase + 4LL * lane;
    const bool tileFull   = (tileBase + 128 <= n);
    const bool valid      = base < n;

    int   key;
    float ar = 0.0f, ag = 0.0f, ab = 0.0f;

    if (tileFull) {
        // seg + w: per-lane coalesced vector loads (streaming).
        const int4   s4 = __ldcs(reinterpret_cast<const int4*>(seg + base));
        const float4 w4 = __ldcs(reinterpret_cast<const float4*>(w + base));

        // rgb: warp-cooperative fully-coalesced load -> smem stage.
        const float4* r4 = reinterpret_cast<const float4*>(rgb) + warp_global * 96;
#pragma unroll
        for (int b = 0; b < 3; b++)
            sbuf[wib][b * 32 + lane] = __ldcs(r4 + b * 32 + lane);
        __syncwarp();

        // Per-lane readback (conflict-free LDS.128 at 48B stride).
        const float4 ra = sbuf[wib][3 * lane + 0];
        const float4 rb = sbuf[wib][3 * lane + 1];
        const float4 rc = sbuf[wib][3 * lane + 2];

        // AoS float3 layout within the 3 float4s:
        //   s0: ra.x ra.y ra.z | s1: ra.w rb.x rb.y
        //   s2: rb.z rb.w rc.x | s3: rc.y rc.z rc.w
        const int   s[4] = {s4.x, s4.y, s4.z, s4.w};
        const float W[4] = {w4.x, w4.y, w4.z, w4.w};
        const float R[4] = {ra.x, ra.w, rb.z, rc.y};
        const float G[4] = {ra.y, rb.x, rb.w, rc.z};
        const float B[4] = {ra.z, rb.y, rc.x, rc.w};

        key = s[0];
#pragma unroll
        for (int i = 0; i < 4; i++) {
            if (s[i] != key) {                 // rare internal boundary
                atomicAdd(out + 3 * key + 0, ar);
                atomicAdd(out + 3 * key + 1, ag);
                atomicAdd(out + 3 * key + 2, ab);
                key = s[i];
                ar = ag = ab = 0.0f;
            }
            ar = fmaf(W[i], R[i], ar);
            ag = fmaf(W[i], G[i], ag);
            ab = fmaf(W[i], B[i], ab);
        }
    } else if (valid) {
        // Scalar tail path (unused for N multiple of 128; kept for safety).
        key = seg[base];
        for (int i = 0; i < 4 && base + i < n; i++) {
            const int si = seg[base + i];
            if (si != key) {
                atomicAdd(out + 3 * key + 0, ar);
                atomicAdd(out + 3 * key + 1, ag);
                atomicAdd(out + 3 * key + 2, ab);
                key = si;
                ar = ag = ab = 0.0f;
            }
            const float ww = w[base + i];
            ar = fmaf(ww, rgb[3 * (base + i) + 0], ar);
            ag = fmaf(ww, rgb[3 * (base + i) + 1], ag);
            ab = fmaf(ww, rgb[3 * (base + i) + 2], ab);
        }
    } else {
        key = -1 - lane;   // unique sentinel: never merges, value is zero
    }

    // Segmented suffix reduction across the warp (keys sorted => runs are
    // lane-contiguous; after 5 steps each run-head holds the run total).
    const unsigned full = 0xffffffffu;
#pragma unroll
    for (int off = 1; off < 32; off <<= 1) {
        const int   nk = __shfl_down_sync(full, key, off);
        const float nr = __shfl_down_sync(full, ar, off);
        const float ng = __shfl_down_sync(full, ag, off);
        const float nb = __shfl_down_sync(full, ab, off);
        if (lane + off < 32 && nk == key) {
            ar += nr; ag += ng; ab += nb;
        }
    }

    const int pk = __shfl_up_sync(full, key, 1);
    const bool head = (lane == 0) || (pk != key);
    if (head && valid) {
        atomicAdd(out + 3 * key + 0, ar);
        atomicAdd(out + 3 * key + 1, ag);
        atomicAdd(out + 3 * key + 2, ab);
    }
}

extern "C" void kernel_launch(void* const* d_in, const int* in_sizes, int n_in,
                              void* d_out, int out_size) {
    const int*   seg = (const int*)d_in[0];
    const float* rgb = (const float*)d_in[1];
    const float* w   = (const float*)d_in[2];
    float*       out = (float*)d_out;
    const int n = in_sizes[0];

    // Zero the (poisoned) output. Graph-capturable memset node; same-stream
    // ordering completes it before the atomics.
    if (out_size > 0)
        cudaMemsetAsync(out, 0, (size_t)out_size * sizeof(float));

    const long long nwarps  = ((long long)n + 127) / 128;
    const long long nthread = nwarps * 32;
    const int nblocks = (int)((nthread + 255) / 256);
    integrate_kernel<<<nblocks, 256>>>(seg, rgb, w, out, n);
}

// round 7
// speedup vs baseline: 1.0144x; 1.0144x over previous
#include <cuda_runtime.h>

// Sorted segment-sum: pred_rgb[r] = sum over samples s of ray r of w_s * rgb_s
// Round 6: R4 structure (R5 smem staging REVERTED - it regressed: L1 57.6%,
// DRAM down) + deeper per-warp MLP.
//  - Warp tile is now 256 samples = two 128-sample half-tiles; ALL 10 global
//    loads (2x int4 seg, 2x float4 w, 6x float4 rgb) are front-batched before
//    any compute -> ~2x outstanding LDGs per warp vs R4, hiding DRAM latency
//    with fewer resident warps (regs ~60, occ ~70% - intentional trade).
//  - Layout identical to R4 (proven best): seg/w coalesced int4/float4, rgb
//    48B-stride float4 direct from global, __ldcs everywhere (169MB > L2).
//  - Per half-tile: register accumulation, rare internal-boundary flush, warp
//    segmented suffix reduction (sorted keys => runs lane-contiguous),
//    head-lane atomicAdd (RED).
//  - cudaMemsetAsync zeroes the poisoned output (ordering before atomics).

__device__ __forceinline__ void reduce_and_flush(
    int key, float ar, float ag, float ab, bool valid, float* __restrict__ out,
    int lane)
{
    const unsigned full = 0xffffffffu;
#pragma unroll
    for (int off = 1; off < 32; off <<= 1) {
        const int   nk = __shfl_down_sync(full, key, off);
        const float nr = __shfl_down_sync(full, ar, off);
        const float ng = __shfl_down_sync(full, ag, off);
        const float nb = __shfl_down_sync(full, ab, off);
        if (lane + off < 32 && nk == key) {
            ar += nr; ag += ng; ab += nb;
        }
    }
    const int pk = __shfl_up_sync(full, key, 1);
    const bool head = (lane == 0) || (pk != key);
    if (head && valid) {
        atomicAdd(out + 3 * key + 0, ar);
        atomicAdd(out + 3 * key + 1, ag);
        atomicAdd(out + 3 * key + 2, ab);
    }
}

__global__ void __launch_bounds__(256) integrate_kernel(
    const int*   __restrict__ seg,
    const float* __restrict__ rgb,
    const float* __restrict__ w,
    float*       __restrict__ out,
    int n)
{
    const int lane = threadIdx.x & 31;
    const long long warp_global =
        ((long long)blockIdx.x * blockDim.x + threadIdx.x) >> 5;
    const long long tileBase = warp_global * 256;
    if (tileBase >= n) return;            // warp-uniform exit only

    if (tileBase + 256 <= n) {
        const long long baseA = tileBase + 4LL * lane;
        const long long baseB = baseA + 128;

        // ---- Front-batched loads for BOTH half-tiles (10 LDGs in flight) ----
        const int4   sA = __ldcs(reinterpret_cast<const int4*>(seg + baseA));
        const int4   sB = __ldcs(reinterpret_cast<const int4*>(seg + baseB));
        const float4 wA = __ldcs(reinterpret_cast<const float4*>(w + baseA));
        const float4 wB = __ldcs(reinterpret_cast<const float4*>(w + baseB));
        const float4* rA4 = reinterpret_cast<const float4*>(rgb + baseA * 3);
        const float4* rB4 = reinterpret_cast<const float4*>(rgb + baseB * 3);
        const float4 rA0 = __ldcs(rA4 + 0);
        const float4 rA1 = __ldcs(rA4 + 1);
        const float4 rA2 = __ldcs(rA4 + 2);
        const float4 rB0 = __ldcs(rB4 + 0);
        const float4 rB1 = __ldcs(rB4 + 1);
        const float4 rB2 = __ldcs(rB4 + 2);

        // ---- Half-tile A ----
        {
            // AoS float3 layout in 3 float4s:
            //   s0: r0.x r0.y r0.z | s1: r0.w r1.x r1.y
            //   s2: r1.z r1.w r2.x | s3: r2.y r2.z r2.w
            const int   s[4] = {sA.x, sA.y, sA.z, sA.w};
            const float W[4] = {wA.x, wA.y, wA.z, wA.w};
            const float R[4] = {rA0.x, rA0.w, rA1.z, rA2.y};
            const float G[4] = {rA0.y, rA1.x, rA1.w, rA2.z};
            const float B[4] = {rA0.z, rA1.y, rA2.x, rA2.w};

            int key = s[0];
            float ar = 0.0f, ag = 0.0f, ab = 0.0f;
#pragma unroll
            for (int i = 0; i < 4; i++) {
                if (s[i] != key) {
                    atomicAdd(out + 3 * key + 0, ar);
                    atomicAdd(out + 3 * key + 1, ag);
                    atomicAdd(out + 3 * key + 2, ab);
                    key = s[i];
                    ar = ag = ab = 0.0f;
                }
                ar = fmaf(W[i], R[i], ar);
                ag = fmaf(W[i], G[i], ag);
                ab = fmaf(W[i], B[i], ab);
            }
            reduce_and_flush(key, ar, ag, ab, true, out, lane);
        }

        // ---- Half-tile B ----
        {
            const int   s[4] = {sB.x, sB.y, sB.z, sB.w};
            const float W[4] = {wB.x, wB.y, wB.z, wB.w};
            const float R[4] = {rB0.x, rB0.w, rB1.z, rB2.y};
            const float G[4] = {rB0.y, rB1.x, rB1.w, rB2.z};
            const float B[4] = {rB0.z, rB1.y, rB2.x, rB2.w};

            int key = s[0];
            float ar = 0.0f, ag = 0.0f, ab = 0.0f;
#pragma unroll
            for (int i = 0; i < 4; i++) {
                if (s[i] != key) {
                    atomicAdd(out + 3 * key + 0, ar);
                    atomicAdd(out + 3 * key + 1, ag);
                    atomicAdd(out + 3 * key + 2, ab);
                    key = s[i];
                    ar = ag = ab = 0.0f;
                }
                ar = fmaf(W[i], R[i], ar);
                ag = fmaf(W[i], G[i], ag);
                ab = fmaf(W[i], B[i], ab);
            }
            reduce_and_flush(key, ar, ag, ab, true, out, lane);
        }
    } else {
        // ---- Partial tile: scalar path per half (N%256==0 in practice) ----
#pragma unroll 1
        for (int h = 0; h < 2; h++) {
            const long long hb = tileBase + 128LL * h;
            if (hb >= n) break;
            const long long base = hb + 4LL * lane;
            const bool valid = base < n;

            int key;
            float ar = 0.0f, ag = 0.0f, ab = 0.0f;
            if (valid) {
                key = seg[base];
                for (int i = 0; i < 4 && base + i < n; i++) {
                    const int si = seg[base + i];
                    if (si != key) {
                        atomicAdd(out + 3 * key + 0, ar);
                        atomicAdd(out + 3 * key + 1, ag);
                        atomicAdd(out + 3 * key + 2, ab);
                        key = si;
                        ar = ag = ab = 0.0f;
                    }
                    const float ww = w[base + i];
                    ar = fmaf(ww, rgb[3 * (base + i) + 0], ar);
                    ag = fmaf(ww, rgb[3 * (base + i) + 1], ag);
                    ab = fmaf(ww, rgb[3 * (base + i) + 2], ab);
                }
            } else {
                key = -1 - lane;   // unique sentinel, zero value
            }
            reduce_and_flush(key, ar, ag, ab, valid, out, lane);
        }
    }
}

extern "C" void kernel_launch(void* const* d_in, const int* in_sizes, int n_in,
                              void* d_out, int out_size) {
    const int*   seg = (const int*)d_in[0];
    const float* rgb = (const float*)d_in[1];
    const float* w   = (const float*)d_in[2];
    float*       out = (float*)d_out;
    const int n = in_sizes[0];

    // Zero the (poisoned) output. Graph-capturable memset node; same-stream
    // ordering completes it before the atomics.
    if (out_size > 0)
        cudaMemsetAsync(out, 0, (size_t)out_size * sizeof(float));

    const long long nwarps  = ((long long)n + 255) / 256;
    const long long nthread = nwarps * 32;
    const int nblocks = (int)((nthread + 255) / 256);
    integrate_kernel<<<nblocks, 256>>>(seg, rgb, w, out, n);
}

// round 9
// speedup vs baseline: 1.0790x; 1.0637x over previous
#include <cuda_runtime.h>

// Sorted segment-sum: pred_rgb[r] = sum over samples s of ray r of w_s * rgb_s
// Round 7 = revert to R4 (best: 29.4us total / 27.5us kernel / 6307 GB/s).
// R5 (smem-staged rgb) and R6 (256-sample tiles, deeper MLP, lower occ) both
// regressed -> R4 is a local optimum sitting at the measured LTS throughput
// cap (~6300 B/cyc). Final configuration:
//  - warp tile = 128 samples, lane chunk = 4: seg int4 + w float4 coalesced,
//    rgb 3x float4 at 48B lane stride, all via __ldcs (169MB read-once > L2).
//  - per-lane register accumulation; rare internal segment boundary flushes
//    directly with atomicAdd (RED).
//  - warp segmented suffix reduction over tail partials (sorted keys => runs
//    are lane-contiguous; 5 shfl.down steps); only run-head lanes emit the
//    3 atomics (~9 RED / 128 samples).
//  - cudaMemsetAsync graph memset node zeroes the poisoned output; same-stream
//    ordering completes it before any atomics.

__global__ void __launch_bounds__(256) integrate_kernel(
    const int*   __restrict__ seg,
    const float* __restrict__ rgb,
    const float* __restrict__ w,
    float*       __restrict__ out,
    int n)
{
    const int lane = threadIdx.x & 31;
    const long long warp_global =
        ((long long)blockIdx.x * blockDim.x + threadIdx.x) >> 5;
    const long long tileBase = warp_global * 128;
    if (tileBase >= n) return;            // warp-uniform exit only

    const long long base = tileBase + 4LL * lane;
    const bool valid = base < n;

    int   key;
    float ar = 0.0f, ag = 0.0f, ab = 0.0f;

    if (valid && base + 4 <= n) {
        // Front-batched streaming loads (evict-first).
        const int4   s4 = __ldcs(reinterpret_cast<const int4*>(seg + base));
        const float4 w4 = __ldcs(reinterpret_cast<const float4*>(w + base));
        const float4* r4 = reinterpret_cast<const float4*>(rgb + base * 3);
        const float4 ra = __ldcs(r4 + 0);
        const float4 rb = __ldcs(r4 + 1);
        const float4 rc = __ldcs(r4 + 2);

        // AoS float3 layout within the 3 float4s:
        //   s0: ra.x ra.y ra.z | s1: ra.w rb.x rb.y
        //   s2: rb.z rb.w rc.x | s3: rc.y rc.z rc.w
        const int   s[4] = {s4.x, s4.y, s4.z, s4.w};
        const float W[4] = {w4.x, w4.y, w4.z, w4.w};
        const float R[4] = {ra.x, ra.w, rb.z, rc.y};
        const float G[4] = {ra.y, rb.x, rb.w, rc.z};
        const float B[4] = {ra.z, rb.y, rc.x, rc.w};

        key = s[0];
#pragma unroll
        for (int i = 0; i < 4; i++) {
            if (s[i] != key) {                 // rare internal boundary
                atomicAdd(out + 3 * key + 0, ar);
                atomicAdd(out + 3 * key + 1, ag);
                atomicAdd(out + 3 * key + 2, ab);
                key = s[i];
                ar = ag = ab = 0.0f;
            }
            ar = fmaf(W[i], R[i], ar);
            ag = fmaf(W[i], G[i], ag);
            ab = fmaf(W[i], B[i], ab);
        }
    } else if (valid) {
        // Scalar tail path.
        key = seg[base];
        for (int i = 0; i < 4 && base + i < n; i++) {
            const int si = seg[base + i];
            if (si != key) {
                atomicAdd(out + 3 * key + 0, ar);
                atomicAdd(out + 3 * key + 1, ag);
                atomicAdd(out + 3 * key + 2, ab);
                key = si;
                ar = ag = ab = 0.0f;
            }
            const float ww = w[base + i];
            ar = fmaf(ww, rgb[3 * (base + i) + 0], ar);
            ag = fmaf(ww, rgb[3 * (base + i) + 1], ag);
            ab = fmaf(ww, rgb[3 * (base + i) + 2], ab);
        }
    } else {
        key = -1 - lane;   // unique sentinel: never merges, value is zero
    }

    // Segmented suffix reduction across the warp (keys sorted => runs are
    // lane-contiguous; after 5 steps each run-head holds the run total).
    const unsigned full = 0xffffffffu;
#pragma unroll
    for (int off = 1; off < 32; off <<= 1) {
        const int   nk = __shfl_down_sync(full, key, off);
        const float nr = __shfl_down_sync(full, ar, off);
        const float ng = __shfl_down_sync(full, ag, off);
        const float nb = __shfl_down_sync(full, ab, off);
        if (lane + off < 32 && nk == key) {
            ar += nr; ag += ng; ab += nb;
        }
    }

    const int pk = __shfl_up_sync(full, key, 1);
    const bool head = (lane == 0) || (pk != key);
    if (head && valid) {
        atomicAdd(out + 3 * key + 0, ar);
        atomicAdd(out + 3 * key + 1, ag);
        atomicAdd(out + 3 * key + 2, ab);
    }
}

extern "C" void kernel_launch(void* const* d_in, const int* in_sizes, int n_in,
                              void* d_out, int out_size) {
    const int*   seg = (const int*)d_in[0];
    const float* rgb = (const float*)d_in[1];
    const float* w   = (const float*)d_in[2];
    float*       out = (float*)d_out;
    const int n = in_sizes[0];

    // Zero the (poisoned) output. Graph-capturable memset node; same-stream
    // ordering completes it before the atomics.
    if (out_size > 0)
        cudaMemsetAsync(out, 0, (size_t)out_size * sizeof(float));

    const long long nwarps  = ((long long)n + 127) / 128;
    const long long nthread = nwarps * 32;
    const int nblocks = (int)((nthread + 255) / 256);
    integrate_kernel<<<nblocks, 256>>>(seg, rgb, w, out, n);
}